// round 1
// baseline (speedup 1.0000x reference)
#include <cuda_runtime.h>
#include <math.h>

// Problem dims (fixed for this problem instance)
#define SEQ   512
#define BATCH 64
#define IND   512
#define HID   1024
#define OUTD  512
#define CDIM  1536          // IND + HID
#define G4    4096          // 4*HID

// ---------------- scratch (static __device__ — no allocs allowed) ----------------
__device__ float g_Gx  [(size_t)SEQ * BATCH * G4];        // 512 MB: x-part of gates + bias
__device__ float g_Hall[(size_t)(SEQ + 1) * BATCH * HID]; // 134 MB: h_0..h_S
__device__ float g_c   [BATCH * HID];                      // cell state
__device__ float g_part[2 * BATCH * G4];                   // K-split partials
__device__ int   g_cnt [64];                               // per-jtile arrival tickets

// ---------------- f32x2 packed-FMA helpers (Blackwell, PTX-only) ----------------
static __device__ __forceinline__ unsigned long long pack2(float x, float y) {
    unsigned long long r;
    asm("mov.b64 %0, {%1, %2};" : "=l"(r) : "f"(x), "f"(y));
    return r;
}
static __device__ __forceinline__ void unpack2(unsigned long long v, float &x, float &y) {
    asm("mov.b64 {%0, %1}, %2;" : "=f"(x), "=f"(y) : "l"(v));
}
static __device__ __forceinline__ unsigned long long fma2(unsigned long long a,
                                                          unsigned long long b,
                                                          unsigned long long c) {
    unsigned long long d;
    asm("fma.rn.f32x2 %0, %1, %2, %3;" : "=l"(d) : "l"(a), "l"(b), "l"(c));
    return d;
}

static __device__ __forceinline__ float sigm(float x) {
    return 1.0f / (1.0f + __expf(-x));
}

// ---------------- init: zero h0, c, tickets ----------------
__global__ void k_init() {
    int idx = blockIdx.x * blockDim.x + threadIdx.x;
    int stride = gridDim.x * blockDim.x;
    for (int i = idx; i < BATCH * HID; i += stride) {
        g_Hall[i] = 0.0f;
        g_c[i] = 0.0f;
    }
    if (idx < 64) g_cnt[idx] = 0;
}

// ---------------- kernel A: Gx = X @ Wx^T + b  (M=32768, N=4096, K=512) ----------------
// tile 128M x 64N, 256 threads, thread = 8 rows x 4 cols, f32x2 row-pairs
__global__ __launch_bounds__(256) void k_pregemm(
    const float* __restrict__ X,
    const float* __restrict__ Wf, const float* __restrict__ bf,
    const float* __restrict__ Wi, const float* __restrict__ bi,
    const float* __restrict__ Wo, const float* __restrict__ bo,
    const float* __restrict__ Wg, const float* __restrict__ bg)
{
    __shared__ float xs[16][132];   // [kk][m], stride 132 keeps 16B alignment
    __shared__ float ws[16][68];    // [kk][n]

    const int tid = threadIdx.x;
    const int m0 = blockIdx.y * 128;
    const int n0 = blockIdx.x * 64;
    const int q  = n0 >> 10;                 // 1024 % 64 == 0 -> tile inside one gate
    const float* Wq = (q == 0) ? Wf : (q == 1) ? Wi : (q == 2) ? Wo : Wg;
    const float* bq = (q == 0) ? bf : (q == 1) ? bi : (q == 2) ? bo : bg;
    const int j0 = n0 & 1023;

    // per-thread load descriptors
    const float* xp[8]; int xm[8], xkk[8];
#pragma unroll
    for (int l = 0; l < 8; l++) {
        int e = tid + l * 256; int m = e >> 4, kk = e & 15;
        xp[l] = X + (size_t)(m0 + m) * IND + kk; xm[l] = m; xkk[l] = kk;
    }
    const float* wp[4]; int wn[4], wkk[4];
#pragma unroll
    for (int l = 0; l < 4; l++) {
        int e = tid + l * 256; int n = e >> 4, kk = e & 15;
        wp[l] = Wq + (size_t)(j0 + n) * CDIM + kk;   // input part: cols 0..511
        wn[l] = n; wkk[l] = kk;
    }

    unsigned long long acc[4][4];
#pragma unroll
    for (int a = 0; a < 4; a++)
#pragma unroll
        for (int b = 0; b < 4; b++) acc[a][b] = 0ull;

    const int trow = tid >> 4;   // 0..15 -> rows trow*8..+7
    const int tcol = tid & 15;   // 0..15 -> cols tcol*4..+3

    float rx[8], rw[4];
#pragma unroll
    for (int l = 0; l < 8; l++) rx[l] = xp[l][0];
#pragma unroll
    for (int l = 0; l < 4; l++) rw[l] = wp[l][0];

    for (int kc = 0; kc < IND; kc += 16) {
#pragma unroll
        for (int l = 0; l < 8; l++) xs[xkk[l]][xm[l]] = rx[l];
#pragma unroll
        for (int l = 0; l < 4; l++) ws[wkk[l]][wn[l]] = rw[l];
        __syncthreads();

        if (kc + 16 < IND) {     // prefetch next chunk (overlaps with compute)
#pragma unroll
            for (int l = 0; l < 8; l++) rx[l] = xp[l][kc + 16];
#pragma unroll
            for (int l = 0; l < 4; l++) rw[l] = wp[l][kc + 16];
        }

#pragma unroll
        for (int kk = 0; kk < 16; kk++) {
            ulonglong2 a01 = *reinterpret_cast<const ulonglong2*>(&xs[kk][trow * 8]);
            ulonglong2 a23 = *reinterpret_cast<const ulonglong2*>(&xs[kk][trow * 8 + 4]);
            float4 bv = *reinterpret_cast<const float4*>(&ws[kk][tcol * 4]);
            unsigned long long bb0 = pack2(bv.x, bv.x);
            unsigned long long bb1 = pack2(bv.y, bv.y);
            unsigned long long bb2 = pack2(bv.z, bv.z);
            unsigned long long bb3 = pack2(bv.w, bv.w);
            acc[0][0] = fma2(a01.x, bb0, acc[0][0]);
            acc[0][1] = fma2(a01.x, bb1, acc[0][1]);
            acc[0][2] = fma2(a01.x, bb2, acc[0][2]);
            acc[0][3] = fma2(a01.x, bb3, acc[0][3]);
            acc[1][0] = fma2(a01.y, bb0, acc[1][0]);
            acc[1][1] = fma2(a01.y, bb1, acc[1][1]);
            acc[1][2] = fma2(a01.y, bb2, acc[1][2]);
            acc[1][3] = fma2(a01.y, bb3, acc[1][3]);
            acc[2][0] = fma2(a23.x, bb0, acc[2][0]);
            acc[2][1] = fma2(a23.x, bb1, acc[2][1]);
            acc[2][2] = fma2(a23.x, bb2, acc[2][2]);
            acc[2][3] = fma2(a23.x, bb3, acc[2][3]);
            acc[3][0] = fma2(a23.y, bb0, acc[3][0]);
            acc[3][1] = fma2(a23.y, bb1, acc[3][1]);
            acc[3][2] = fma2(a23.y, bb2, acc[3][2]);
            acc[3][3] = fma2(a23.y, bb3, acc[3][3]);
        }
        __syncthreads();
    }

#pragma unroll
    for (int rp = 0; rp < 4; rp++) {
        int r0 = trow * 8 + rp * 2;
#pragma unroll
        for (int c = 0; c < 4; c++) {
            float v0, v1;
            unpack2(acc[rp][c], v0, v1);
            int n = n0 + tcol * 4 + c;
            float bias = bq[j0 + tcol * 4 + c];
            size_t base = (size_t)(m0 + r0) * G4 + n;
            g_Gx[base]      = v0 + bias;
            g_Gx[base + G4] = v1 + bias;
        }
    }
}

// ---------------- kernel B: one recurrence step ----------------
// grid (64 jtiles, 2 K-halves). tile 64B x 64N (4 gates x 16 j), K-half = 512.
// Last-arriving block per jtile reduces the two partials + Gx and does the
// activation / cell / hidden update (fused — one kernel node per step).
__global__ __launch_bounds__(256) void k_step(
    int t,
    const float* __restrict__ Wf, const float* __restrict__ Wi,
    const float* __restrict__ Wo, const float* __restrict__ Wg)
{
    __shared__ float hs[16][68];   // [kk][b]
    __shared__ float ws[16][68];   // [kk][n]
    __shared__ int s_old;

    const int tid  = threadIdx.x;
    const int jt   = blockIdx.x;   // 0..63
    const int half = blockIdx.y;   // 0..1
    const int j0   = jt * 16;
    const float* Hprev = g_Hall + (size_t)t * (BATCH * HID);

    const float* hp[4]; int hb[4], hkk[4];
#pragma unroll
    for (int l = 0; l < 4; l++) {
        int e = tid + l * 256; int b = e >> 4, kk = e & 15;
        hp[l] = Hprev + b * HID + half * 512 + kk; hb[l] = b; hkk[l] = kk;
    }
    const float* wp[4]; int wn[4], wkk[4];
#pragma unroll
    for (int l = 0; l < 4; l++) {
        int e = tid + l * 256; int n = e >> 4, kk = e & 15;
        int q = n >> 4, jn = n & 15;
        const float* Wq = (q == 0) ? Wf : (q == 1) ? Wi : (q == 2) ? Wo : Wg;
        wp[l] = Wq + (size_t)(j0 + jn) * CDIM + IND + half * 512 + kk;  // h-part cols
        wn[l] = n; wkk[l] = kk;
    }

    unsigned long long acc[2][4];
#pragma unroll
    for (int a = 0; a < 2; a++)
#pragma unroll
        for (int b = 0; b < 4; b++) acc[a][b] = 0ull;

    const int trow = tid >> 4;   // rows trow*4..+3 (batch)
    const int tcol = tid & 15;   // cols tcol*4..+3

    float rh[4], rw[4];
#pragma unroll
    for (int l = 0; l < 4; l++) rh[l] = hp[l][0];
#pragma unroll
    for (int l = 0; l < 4; l++) rw[l] = wp[l][0];

    for (int kc = 0; kc < 512; kc += 16) {
#pragma unroll
        for (int l = 0; l < 4; l++) hs[hkk[l]][hb[l]] = rh[l];
#pragma unroll
        for (int l = 0; l < 4; l++) ws[wkk[l]][wn[l]] = rw[l];
        __syncthreads();

        if (kc + 16 < 512) {
#pragma unroll
            for (int l = 0; l < 4; l++) rh[l] = hp[l][kc + 16];
#pragma unroll
            for (int l = 0; l < 4; l++) rw[l] = wp[l][kc + 16];
        }

#pragma unroll
        for (int kk = 0; kk < 16; kk++) {
            ulonglong2 a2 = *reinterpret_cast<const ulonglong2*>(&hs[kk][trow * 4]);
            float4 bv = *reinterpret_cast<const float4*>(&ws[kk][tcol * 4]);
            unsigned long long bb0 = pack2(bv.x, bv.x);
            unsigned long long bb1 = pack2(bv.y, bv.y);
            unsigned long long bb2 = pack2(bv.z, bv.z);
            unsigned long long bb3 = pack2(bv.w, bv.w);
            acc[0][0] = fma2(a2.x, bb0, acc[0][0]);
            acc[0][1] = fma2(a2.x, bb1, acc[0][1]);
            acc[0][2] = fma2(a2.x, bb2, acc[0][2]);
            acc[0][3] = fma2(a2.x, bb3, acc[0][3]);
            acc[1][0] = fma2(a2.y, bb0, acc[1][0]);
            acc[1][1] = fma2(a2.y, bb1, acc[1][1]);
            acc[1][2] = fma2(a2.y, bb2, acc[1][2]);
            acc[1][3] = fma2(a2.y, bb3, acc[1][3]);
        }
        __syncthreads();
    }

    // write K-half partial
    float* part = g_part + (size_t)half * (BATCH * G4);
#pragma unroll
    for (int rp = 0; rp < 2; rp++) {
        int b = trow * 4 + rp * 2;
#pragma unroll
        for (int c = 0; c < 4; c++) {
            float v0, v1;
            unpack2(acc[rp][c], v0, v1);
            int nl = tcol * 4 + c;
            int qg = nl >> 4, jn = nl & 15;
            int ng = qg * 1024 + j0 + jn;
            part[(size_t)b * G4 + ng]       = v0;
            part[(size_t)(b + 1) * G4 + ng] = v1;
        }
    }

    __threadfence();
    __syncthreads();
    if (tid == 0) s_old = atomicAdd(&g_cnt[jt], 1);
    __syncthreads();
    if (s_old != 2 * t + 1) return;   // not the last arrival for this jtile
    __threadfence();                   // acquire: make the other half's writes visible

    // finalize: gates -> activations -> c,h update (this block owns j0..j0+15, all b)
    const float* p0 = g_part;
    const float* p1 = g_part + (size_t)(BATCH * G4);
    float* Hn = g_Hall + (size_t)(t + 1) * (BATCH * HID);
#pragma unroll
    for (int l = 0; l < 4; l++) {
        int e = tid + l * 256;
        int b = e >> 4, jn = e & 15;
        int j = j0 + jn;
        size_t gbase = (size_t)(t * BATCH + b) * G4;
        float gg[4];
#pragma unroll
        for (int qg = 0; qg < 4; qg++) {
            int n = qg * 1024 + j;
            gg[qg] = g_Gx[gbase + n] + p0[(size_t)b * G4 + n] + p1[(size_t)b * G4 + n];
        }
        float f  = sigm(gg[0]);
        float ii = sigm(gg[1]);
        float oo = sigm(gg[2]);
        float gt = tanhf(gg[3]);
        int ci = b * HID + j;
        float cn = f * g_c[ci] + ii * gt;
        g_c[ci] = cn;
        Hn[ci] = oo * tanhf(cn);
    }
}

// ---------------- kernel C: out = Hall[1..] @ Wy^T + by  (M=32768, N=512, K=1024) ----------------
__global__ __launch_bounds__(256) void k_out(
    const float* __restrict__ Wy, const float* __restrict__ by,
    float* __restrict__ Yout)
{
    __shared__ float xs[16][132];
    __shared__ float ws[16][68];

    const int tid = threadIdx.x;
    const int m0 = blockIdx.y * 128;
    const int n0 = blockIdx.x * 64;
    const float* Hsrc = g_Hall + (size_t)(BATCH * HID);  // rows m = t*B+b, stride HID

    const float* xp[8]; int xm[8], xkk[8];
#pragma unroll
    for (int l = 0; l < 8; l++) {
        int e = tid + l * 256; int m = e >> 4, kk = e & 15;
        xp[l] = Hsrc + (size_t)(m0 + m) * HID + kk; xm[l] = m; xkk[l] = kk;
    }
    const float* wp[4]; int wn[4], wkk[4];
#pragma unroll
    for (int l = 0; l < 4; l++) {
        int e = tid + l * 256; int n = e >> 4, kk = e & 15;
        wp[l] = Wy + (size_t)(n0 + n) * HID + kk; wn[l] = n; wkk[l] = kk;
    }

    unsigned long long acc[4][4];
#pragma unroll
    for (int a = 0; a < 4; a++)
#pragma unroll
        for (int b = 0; b < 4; b++) acc[a][b] = 0ull;

    const int trow = tid >> 4;
    const int tcol = tid & 15;

    float rx[8], rw[4];
#pragma unroll
    for (int l = 0; l < 8; l++) rx[l] = xp[l][0];
#pragma unroll
    for (int l = 0; l < 4; l++) rw[l] = wp[l][0];

    for (int kc = 0; kc < HID; kc += 16) {
#pragma unroll
        for (int l = 0; l < 8; l++) xs[xkk[l]][xm[l]] = rx[l];
#pragma unroll
        for (int l = 0; l < 4; l++) ws[wkk[l]][wn[l]] = rw[l];
        __syncthreads();

        if (kc + 16 < HID) {
#pragma unroll
            for (int l = 0; l < 8; l++) rx[l] = xp[l][kc + 16];
#pragma unroll
            for (int l = 0; l < 4; l++) rw[l] = wp[l][kc + 16];
        }

#pragma unroll
        for (int kk = 0; kk < 16; kk++) {
            ulonglong2 a01 = *reinterpret_cast<const ulonglong2*>(&xs[kk][trow * 8]);
            ulonglong2 a23 = *reinterpret_cast<const ulonglong2*>(&xs[kk][trow * 8 + 4]);
            float4 bv = *reinterpret_cast<const float4*>(&ws[kk][tcol * 4]);
            unsigned long long bb0 = pack2(bv.x, bv.x);
            unsigned long long bb1 = pack2(bv.y, bv.y);
            unsigned long long bb2 = pack2(bv.z, bv.z);
            unsigned long long bb3 = pack2(bv.w, bv.w);
            acc[0][0] = fma2(a01.x, bb0, acc[0][0]);
            acc[0][1] = fma2(a01.x, bb1, acc[0][1]);
            acc[0][2] = fma2(a01.x, bb2, acc[0][2]);
            acc[0][3] = fma2(a01.x, bb3, acc[0][3]);
            acc[1][0] = fma2(a01.y, bb0, acc[1][0]);
            acc[1][1] = fma2(a01.y, bb1, acc[1][1]);
            acc[1][2] = fma2(a01.y, bb2, acc[1][2]);
            acc[1][3] = fma2(a01.y, bb3, acc[1][3]);
            acc[2][0] = fma2(a23.x, bb0, acc[2][0]);
            acc[2][1] = fma2(a23.x, bb1, acc[2][1]);
            acc[2][2] = fma2(a23.x, bb2, acc[2][2]);
            acc[2][3] = fma2(a23.x, bb3, acc[2][3]);
            acc[3][0] = fma2(a23.y, bb0, acc[3][0]);
            acc[3][1] = fma2(a23.y, bb1, acc[3][1]);
            acc[3][2] = fma2(a23.y, bb2, acc[3][2]);
            acc[3][3] = fma2(a23.y, bb3, acc[3][3]);
        }
        __syncthreads();
    }

#pragma unroll
    for (int rp = 0; rp < 4; rp++) {
        int r0 = trow * 8 + rp * 2;
#pragma unroll
        for (int c = 0; c < 4; c++) {
            float v0, v1;
            unpack2(acc[rp][c], v0, v1);
            int n = n0 + tcol * 4 + c;
            float bias = by[n];
            size_t base = (size_t)(m0 + r0) * OUTD + n;
            Yout[base]        = v0 + bias;
            Yout[base + OUTD] = v1 + bias;
        }
    }
}

// ---------------- launch ----------------
extern "C" void kernel_launch(void* const* d_in, const int* in_sizes, int n_in,
                              void* d_out, int out_size) {
    const float* x  = (const float*)d_in[0];
    const float* Wf = (const float*)d_in[1];
    const float* bf = (const float*)d_in[2];
    const float* Wi = (const float*)d_in[3];
    const float* bi = (const float*)d_in[4];
    const float* Wo = (const float*)d_in[5];
    const float* bo = (const float*)d_in[6];
    const float* Wg = (const float*)d_in[7];
    const float* bg = (const float*)d_in[8];
    const float* Wy = (const float*)d_in[9];
    const float* by = (const float*)d_in[10];
    float* out = (float*)d_out;

    k_init<<<64, 256>>>();
    k_pregemm<<<dim3(64, 256), 256>>>(x, Wf, bf, Wi, bi, Wo, bo, Wg, bg);
    for (int t = 0; t < SEQ; t++)
        k_step<<<dim3(64, 2), 256>>>(t, Wf, Wi, Wo, Wg);
    k_out<<<dim3(8, 256), 256>>>(Wy, by, out);
}